// round 17
// baseline (speedup 1.0000x reference)
#include <cuda_runtime.h>
#include <cuda_bf16.h>
#include <cuda_fp16.h>
#include <cstdint>

// ---------------- problem constants ----------------
constexpr int TN   = 30000;
constexpr int TE   = 480000;
constexpr int TET  = TE + TN;
constexpr int TG   = 64;

// ---------------- static scratch ----------------
__device__ __half2 d_xl2[TN * 256];      // fp16 xl (512 ch as half2 pairs)
__device__ float   d_xr[TN * 512];
__device__ int     d_deg[TN];
__device__ int     d_off[TN + 1];
__device__ int     d_cur[TN];
__device__ int     d_csrc[TET];
__device__ float   d_pool[TG * 32];
__device__ float   d_cnt[TG];
// bf16 split operands
__device__ __nv_bfloat16 d_xhi[TN * 128];
__device__ __nv_bfloat16 d_xlo[TN * 128];
__device__ __nv_bfloat16 d_hhi[TN * 32];
__device__ __nv_bfloat16 d_hlo[TN * 32];
__device__ __nv_bfloat16 d_wl1hi[512 * 128];
__device__ __nv_bfloat16 d_wl1lo[512 * 128];
__device__ __nv_bfloat16 d_wr1hi[512 * 128];
__device__ __nv_bfloat16 d_wr1lo[512 * 128];
__device__ __nv_bfloat16 d_wl2hi[512 * 32];
__device__ __nv_bfloat16 d_wl2lo[512 * 32];
__device__ __nv_bfloat16 d_wr2hi[512 * 32];
__device__ __nv_bfloat16 d_wr2lo[512 * 32];

// ---------------- warp-MMA helpers (arch-portable: sm_80+) ----------------
__device__ __forceinline__ uint32_t smem_u32(const void* p) {
    uint32_t a;
    asm("{ .reg .u64 t; cvta.to.shared.u64 t, %1; cvt.u32.u64 %0, t; }" : "=r"(a) : "l"(p));
    return a;
}
__device__ __forceinline__ void ldm_x4(uint32_t& r0, uint32_t& r1, uint32_t& r2,
                                       uint32_t& r3, uint32_t addr) {
    asm volatile("ldmatrix.sync.aligned.m8n8.x4.shared.b16 {%0,%1,%2,%3}, [%4];"
                 : "=r"(r0), "=r"(r1), "=r"(r2), "=r"(r3) : "r"(addr));
}
__device__ __forceinline__ void mma_16816(float* c, const uint32_t* a, const uint32_t* b) {
    asm volatile(
        "mma.sync.aligned.m16n8k16.row.col.f32.bf16.bf16.f32 "
        "{%0,%1,%2,%3}, {%4,%5,%6,%7}, {%8,%9}, {%0,%1,%2,%3};"
        : "+f"(c[0]), "+f"(c[1]), "+f"(c[2]), "+f"(c[3])
        : "r"(a[0]), "r"(a[1]), "r"(a[2]), "r"(a[3]), "r"(b[0]), "r"(b[1]));
}
__device__ __forceinline__ void cp16(uint32_t dst, const void* src, int sz) {
    asm volatile("cp.async.cg.shared.global [%0], [%1], 16, %2;"
                 :: "r"(dst), "l"(src), "r"(sz));
}
__device__ __forceinline__ void cp_commit() {
    asm volatile("cp.async.commit_group;" ::: "memory");
}
template<int Nwait>
__device__ __forceinline__ void cp_wait() {
    asm volatile("cp.async.wait_group %0;" :: "n"(Nwait) : "memory");
}

// ---------------- tensor-core GEMM via mma.sync (HMMA) ----------------
// Block tile 128(M) x 64(N), 2 blocks/SM (smem 61KB total, ~95 regs/thread).
constexpr int PAD = 40;                   // conflict-free ldmatrix row stride (bf16)
constexpr int A_BYTES = 128 * PAD * 2;    // 10240
constexpr int B_BYTES = 64 * PAD * 2;     // 5120
constexpr int STAGE_BYTES = 2 * A_BYTES + 2 * B_BYTES;   // 30720
// stage offsets: Ah=0, Al=10240, Bh=20480, Bl=25600

template<int K>
__global__ __launch_bounds__(256, 2) void k_gemm_mma(
    const __nv_bfloat16* __restrict__ Ahi, const __nv_bfloat16* __restrict__ Alo,
    const __nv_bfloat16* __restrict__ WLhi, const __nv_bfloat16* __restrict__ WLlo,
    const __nv_bfloat16* __restrict__ WRhi, const __nv_bfloat16* __restrict__ WRlo,
    const float* __restrict__ biasL, const float* __restrict__ biasR,
    __half2* __restrict__ outL, float* __restrict__ outR, int M) {
    extern __shared__ char smem[];
    constexpr int NSTAGE = K / 32;

    int tid = threadIdx.x, wid = tid >> 5, lane = tid & 31;
    bool isR = blockIdx.x >= 8;
    int n0 = (blockIdx.x & 7) * 64;
    int row0 = blockIdx.y * 128;
    const __nv_bfloat16* Bh = isR ? WRhi : WLhi;
    const __nv_bfloat16* Bl = isR ? WRlo : WLlo;
    const float* bias = isR ? biasR : biasL;

    int warp_m = wid & 3, warp_n = wid >> 2;     // warp tile 32(M) x 32(N)
    uint32_t sbase = smem_u32(smem);

    float acc[2][4][4];
#pragma unroll
    for (int i = 0; i < 2; i++)
#pragma unroll
        for (int j = 0; j < 4; j++)
#pragma unroll
            for (int c = 0; c < 4; c++) acc[i][j][c] = 0.f;

    // staging coords: A -> 2 chunks/thread/matrix; B -> 1 chunk/thread/matrix
    int ar_[2], akc_[2];
#pragma unroll
    for (int it = 0; it < 2; it++) {
        int lin = tid + it * 256;
        ar_[it] = lin >> 2;
        akc_[it] = (lin & 3) * 8;
    }
    int br_ = tid >> 2, bkc_ = (tid & 3) * 8;

    auto prefetch = [&](int buf, int k0) {
        uint32_t base = sbase + buf * STAGE_BYTES;
#pragma unroll
        for (int it = 0; it < 2; it++) {
            int r = ar_[it], kc = akc_[it];
            uint32_t o = (uint32_t)(r * PAD + kc) * 2;
            int sz = (row0 + r < M) ? 16 : 0;
            cp16(base + o,           Ahi + (size_t)(row0 + r) * K + k0 + kc, sz);
            cp16(base + A_BYTES + o, Alo + (size_t)(row0 + r) * K + k0 + kc, sz);
        }
        {
            uint32_t o = (uint32_t)(br_ * PAD + bkc_) * 2;
            cp16(base + 2 * A_BYTES + o,
                 Bh + (size_t)(n0 + br_) * K + k0 + bkc_, 16);
            cp16(base + 2 * A_BYTES + B_BYTES + o,
                 Bl + (size_t)(n0 + br_) * K + k0 + bkc_, 16);
        }
        cp_commit();
    };

    prefetch(0, 0);

    for (int i = 0; i < NSTAGE; i++) {
        cp_wait<0>();
        __syncthreads();
        if (i + 1 < NSTAGE) prefetch((i + 1) & 1, (i + 1) * 32);

        uint32_t base = sbase + (i & 1) * STAGE_BYTES;
        uint32_t ah_b = base, al_b = base + A_BYTES;
        uint32_t bh_b = base + 2 * A_BYTES, bl_b = base + 2 * A_BYTES + B_BYTES;

#pragma unroll
        for (int ks = 0; ks < 32; ks += 16) {
            uint32_t a_h[2][4], a_l[2][4];
#pragma unroll
            for (int ai = 0; ai < 2; ai++) {
                int arow = warp_m * 32 + ai * 16 + (lane & 15);
                uint32_t o = (uint32_t)(arow * PAD + ks + (lane >> 4) * 8) * 2;
                ldm_x4(a_h[ai][0], a_h[ai][1], a_h[ai][2], a_h[ai][3], ah_b + o);
                ldm_x4(a_l[ai][0], a_l[ai][1], a_l[ai][2], a_l[ai][3], al_b + o);
            }
            uint32_t b_h[4][2], b_l[4][2];
#pragma unroll
            for (int pr = 0; pr < 2; pr++) {
                int brow = warp_n * 32 + pr * 16 + ((lane >> 4) & 1) * 8 + (lane & 7);
                int koff = ks + ((lane >> 3) & 1) * 8;
                uint32_t o = (uint32_t)(brow * PAD + koff) * 2;
                ldm_x4(b_h[pr * 2][0], b_h[pr * 2][1],
                       b_h[pr * 2 + 1][0], b_h[pr * 2 + 1][1], bh_b + o);
                ldm_x4(b_l[pr * 2][0], b_l[pr * 2][1],
                       b_l[pr * 2 + 1][0], b_l[pr * 2 + 1][1], bl_b + o);
            }
#pragma unroll
            for (int ai = 0; ai < 2; ai++)
#pragma unroll
                for (int j = 0; j < 4; j++) {
                    float* c = acc[ai][j];
                    mma_16816(c, a_h[ai], b_h[j]);
                    mma_16816(c, a_h[ai], b_l[j]);
                    mma_16816(c, a_l[ai], b_h[j]);
                }
        }
        __syncthreads();
    }

    int grp = lane >> 2, tig = lane & 3;
#pragma unroll
    for (int i = 0; i < 2; i++) {
        int r_lo = row0 + warp_m * 32 + i * 16 + grp;
#pragma unroll
        for (int j = 0; j < 4; j++) {
            int col = n0 + warp_n * 32 + j * 8 + tig * 2;
            float b0 = bias[col], b1 = bias[col + 1];
            if (isR) {
                if (r_lo < M)
                    *(float2*)(outR + (size_t)r_lo * 512 + col) =
                        make_float2(acc[i][j][0] + b0, acc[i][j][1] + b1);
                if (r_lo + 8 < M)
                    *(float2*)(outR + (size_t)(r_lo + 8) * 512 + col) =
                        make_float2(acc[i][j][2] + b0, acc[i][j][3] + b1);
            } else {
                if (r_lo < M)
                    outL[(size_t)r_lo * 256 + col / 2] =
                        __floats2half2_rn(acc[i][j][0] + b0, acc[i][j][1] + b1);
                if (r_lo + 8 < M)
                    outL[(size_t)(r_lo + 8) * 256 + col / 2] =
                        __floats2half2_rn(acc[i][j][2] + b0, acc[i][j][3] + b1);
            }
        }
    }
}

// ---------------- merged split kernel ----------------
// covers: x (N*128, straight), Wl1/Wr1 (128x512, transpose), Wl2/Wr2 (32x512, transpose)
__global__ void k_split_all(const float* __restrict__ x, int NX,
                            const float* __restrict__ Wl1, const float* __restrict__ Wr1,
                            const float* __restrict__ Wl2, const float* __restrict__ Wr2,
                            __nv_bfloat16* xhi, __nv_bfloat16* xlo,
                            __nv_bfloat16* wl1h, __nv_bfloat16* wl1l,
                            __nv_bfloat16* wr1h, __nv_bfloat16* wr1l,
                            __nv_bfloat16* wl2h, __nv_bfloat16* wl2l,
                            __nv_bfloat16* wr2h, __nv_bfloat16* wr2l) {
    int i = blockIdx.x * 256 + threadIdx.x;
    float v;
    __nv_bfloat16* ph;
    __nv_bfloat16* pl;
    int idx;
    if (i < NX) {
        v = x[i]; ph = xhi; pl = xlo; idx = i;
    } else {
        int j = i - NX;
        if (j < 131072) {          // Wl1 / Wr1: 128x512 each
            const float* W = (j < 65536) ? Wl1 : Wr1;
            ph = (j < 65536) ? wl1h : wr1h;
            pl = (j < 65536) ? wl1l : wr1l;
            int jj = j & 65535;
            int k = jj >> 9, n = jj & 511;
            v = W[jj];
            idx = n * 128 + k;
        } else if (j < 163840) {   // Wl2 / Wr2: 32x512 each
            int j2 = j - 131072;
            const float* W = (j2 < 16384) ? Wl2 : Wr2;
            ph = (j2 < 16384) ? wl2h : wr2h;
            pl = (j2 < 16384) ? wl2l : wr2l;
            int jj = j2 & 16383;
            int k = jj >> 9, n = jj & 511;
            v = W[jj];
            idx = n * 32 + k;
        } else return;
    }
    __nv_bfloat16 h = __float2bfloat16(v);
    ph[idx] = h;
    pl[idx] = __float2bfloat16(v - __bfloat162float(h));
}

// ---------------- combined zero kernels ----------------
__global__ void k_zero_csr(int* deg, int* cur, int n) {
    int i = blockIdx.x * blockDim.x + threadIdx.x;
    if (i < n) { deg[i] = 0; cur[i] = 0; }
}
__global__ void k_zero_pool(float* pool, float* cnt) {
    int i = blockIdx.x * blockDim.x + threadIdx.x;
    if (i < TG * 32) pool[i] = 0.f;
    if (i < TG) cnt[i] = 0.f;
}

// ---------------- CSR build ----------------
__global__ void k_count(const int* __restrict__ dstA, int E0, int Etot, int* deg) {
    int e = blockIdx.x * blockDim.x + threadIdx.x;
    if (e >= Etot) return;
    int d = (e < E0) ? dstA[e] : (e - E0);
    atomicAdd(&deg[d], 1);
}
__global__ void k_scan(const int* __restrict__ deg, int* __restrict__ off, int n) {
    __shared__ int warpsums[32];
    __shared__ int s_carry;
    int tid = threadIdx.x, lane = tid & 31, wid = tid >> 5;
    if (tid == 0) { s_carry = 0; off[0] = 0; }
    __syncthreads();
    for (int base = 0; base < n; base += 1024) {
        int i = base + tid;
        int x = (i < n) ? deg[i] : 0;
#pragma unroll
        for (int o = 1; o < 32; o <<= 1) {
            int t = __shfl_up_sync(0xffffffffu, x, o);
            if (lane >= o) x += t;
        }
        if (lane == 31) warpsums[wid] = x;
        __syncthreads();
        if (wid == 0) {
            int y = warpsums[lane];
#pragma unroll
            for (int o = 1; o < 32; o <<= 1) {
                int t = __shfl_up_sync(0xffffffffu, y, o);
                if (lane >= o) y += t;
            }
            warpsums[lane] = y;
        }
        __syncthreads();
        int prefix = s_carry + (wid ? warpsums[wid - 1] : 0);
        if (i < n) off[i + 1] = prefix + x;
        __syncthreads();
        if (tid == 1023) s_carry = prefix + x;
        __syncthreads();
    }
}
__global__ void k_scatter(const int* __restrict__ srcA, const int* __restrict__ dstA,
                          int E0, int Etot, const int* __restrict__ off,
                          int* cur, int* csrc) {
    int e = blockIdx.x * blockDim.x + threadIdx.x;
    if (e >= Etot) return;
    int s, d;
    if (e < E0) { s = srcA[e]; d = dstA[e]; } else { s = d = e - E0; }
    int pos = off[d] + atomicAdd(&cur[d], 1);
    csrc[pos] = s;
}

// ---------------- fused GATv2 edge pass (one warp per dst node) ----------------
// No running max (scores ~N(0,1), exp cannot overflow; softmax shift-invariant).
__global__ __launch_bounds__(256) void k_fused(const __half2* __restrict__ xl2,
                                               const float* __restrict__ xr,
                                               const float* __restrict__ att,
                                               const int* __restrict__ off,
                                               const int* __restrict__ csrc,
                                               const float* __restrict__ bias,
                                               __nv_bfloat16* __restrict__ hi,
                                               __nv_bfloat16* __restrict__ lo,
                                               const int* __restrict__ batch,
                                               float* __restrict__ pool,
                                               float* __restrict__ cnt,
                                               int N) {
    int w = (blockIdx.x * 256 + threadIdx.x) >> 5;
    int lane = threadIdx.x & 31;
    if (w >= N) return;

    const float4* att4 = (const float4*)att;
    const float4* xr4  = (const float4*)(xr + (size_t)w * 512);
    float attA[8], attB[8], xrA[8], xrB[8];
    {
        float4 t0 = att4[lane * 2], t1 = att4[lane * 2 + 1];
        float4 t2 = att4[64 + lane * 2], t3 = att4[64 + lane * 2 + 1];
        attA[0]=t0.x; attA[1]=t0.y; attA[2]=t0.z; attA[3]=t0.w;
        attA[4]=t1.x; attA[5]=t1.y; attA[6]=t1.z; attA[7]=t1.w;
        attB[0]=t2.x; attB[1]=t2.y; attB[2]=t2.z; attB[3]=t2.w;
        attB[4]=t3.x; attB[5]=t3.y; attB[6]=t3.z; attB[7]=t3.w;
        float4 u0 = xr4[lane * 2], u1 = xr4[lane * 2 + 1];
        float4 u2 = xr4[64 + lane * 2], u3 = xr4[64 + lane * 2 + 1];
        xrA[0]=u0.x; xrA[1]=u0.y; xrA[2]=u0.z; xrA[3]=u0.w;
        xrA[4]=u1.x; xrA[5]=u1.y; xrA[6]=u1.z; xrA[7]=u1.w;
        xrB[0]=u2.x; xrB[1]=u2.y; xrB[2]=u2.z; xrB[3]=u2.w;
        xrB[4]=u3.x; xrB[5]=u3.y; xrB[6]=u3.z; xrB[7]=u3.w;
    }

    float ssumA = 0.f, ssumB = 0.f;
    float accA[8], accB[8];
#pragma unroll
    for (int c = 0; c < 8; c++) { accA[c] = 0.f; accB[c] = 0.f; }

    int beg = off[w], end = off[w + 1];
    const uint4* xbase = (const uint4*)xl2;

    for (int i = beg; i < end; i++) {
        int s = __ldg(csrc + i);
        const uint4* xp = xbase + (size_t)s * 64;
        uint4 va = __ldg(xp + lane);
        uint4 vb = __ldg(xp + 32 + lane);
        float xa[8], xb[8];
        {
            float2 f;
            f = __half22float2(*(__half2*)&va.x); xa[0]=f.x; xa[1]=f.y;
            f = __half22float2(*(__half2*)&va.y); xa[2]=f.x; xa[3]=f.y;
            f = __half22float2(*(__half2*)&va.z); xa[4]=f.x; xa[5]=f.y;
            f = __half22float2(*(__half2*)&va.w); xa[6]=f.x; xa[7]=f.y;
            f = __half22float2(*(__half2*)&vb.x); xb[0]=f.x; xb[1]=f.y;
            f = __half22float2(*(__half2*)&vb.y); xb[2]=f.x; xb[3]=f.y;
            f = __half22float2(*(__half2*)&vb.z); xb[4]=f.x; xb[5]=f.y;
            f = __half22float2(*(__half2*)&vb.w); xb[6]=f.x; xb[7]=f.y;
        }
        float pA = 0.f, pB = 0.f;
#pragma unroll
        for (int c = 0; c < 8; c++) {
            float ta = xa[c] + xrA[c];
            ta = ta > 0.f ? ta : 0.2f * ta;
            pA = fmaf(ta, attA[c], pA);
            float tb = xb[c] + xrB[c];
            tb = tb > 0.f ? tb : 0.2f * tb;
            pB = fmaf(tb, attB[c], pB);
        }
        pA += __shfl_xor_sync(0xffffffffu, pA, 1);
        pA += __shfl_xor_sync(0xffffffffu, pA, 2);
        pB += __shfl_xor_sync(0xffffffffu, pB, 1);
        pB += __shfl_xor_sync(0xffffffffu, pB, 2);
        float exA = __expf(pA);
        float exB = __expf(pB);
        ssumA += exA;
        ssumB += exB;
#pragma unroll
        for (int c = 0; c < 8; c++) {
            accA[c] = fmaf(exA, xa[c], accA[c]);
            accB[c] = fmaf(exB, xb[c], accB[c]);
        }
    }

    float invA = 1.0f / ssumA, invB = 1.0f / ssumB;
    float o[8];
#pragma unroll
    for (int c = 0; c < 8; c++) o[c] = accA[c] * invA + accB[c] * invB;
#pragma unroll
    for (int d = 4; d <= 16; d <<= 1)
#pragma unroll
        for (int c = 0; c < 8; c++)
            o[c] += __shfl_xor_sync(0xffffffffu, o[c], d);

    if (lane < 4) {
        float r[8];
#pragma unroll
        for (int c = 0; c < 8; c++) {
            float v = o[c] * (1.0f / 16.0f) + bias[lane * 8 + c];
            r[c] = v > 0.f ? v : 0.01f * v;
        }
        if (hi) {
            __nv_bfloat16 hbuf[8], lbuf[8];
#pragma unroll
            for (int c = 0; c < 8; c++) {
                __nv_bfloat16 h = __float2bfloat16(r[c]);
                hbuf[c] = h;
                lbuf[c] = __float2bfloat16(r[c] - __bfloat162float(h));
            }
            *(uint4*)(hi + (size_t)w * 32 + lane * 8) = *(uint4*)hbuf;
            *(uint4*)(lo + (size_t)w * 32 + lane * 8) = *(uint4*)lbuf;
        }
        if (pool) {
            int g = batch[w];
            float* pp = pool + g * 32 + lane * 8;
#pragma unroll
            for (int c = 0; c < 8; c++) atomicAdd(pp + c, r[c]);
            if (lane == 0) atomicAdd(&cnt[g], 1.f);
        }
    }
}

// ---------------- classifier ----------------
__global__ void k_logits(const float* __restrict__ pool, const float* __restrict__ cnt,
                         const float* __restrict__ Wc, const float* __restrict__ bc,
                         float* __restrict__ out) {
    int t = threadIdx.x;
    if (t >= 640) return;
    int g = t / 10, j = t % 10;
    float cn = fmaxf(cnt[g], 1.f);
    float s = 0.f;
#pragma unroll
    for (int c = 0; c < 32; c++)
        s += (pool[g * 32 + c] / cn) * Wc[c * 10 + j];
    out[t] = s + bc[j];
}

// ---------------- persistent stream/event ----------------
struct SideStream {
    cudaStream_t s;
    cudaEvent_t ev_fork, ev_join;
    SideStream() {
        cudaStreamCreateWithFlags(&s, cudaStreamNonBlocking);
        cudaEventCreateWithFlags(&ev_fork, cudaEventDisableTiming);
        cudaEventCreateWithFlags(&ev_join, cudaEventDisableTiming);
    }
};
static SideStream g_side;

// ---------------- launch ----------------
extern "C" void kernel_launch(void* const* d_in, const int* in_sizes, int n_in,
                              void* d_out, int out_size) {
    const float* x    = (const float*)d_in[0];
    const float* Wl1  = (const float*)d_in[1];
    const float* bl1  = (const float*)d_in[2];
    const float* Wr1  = (const float*)d_in[3];
    const float* br1  = (const float*)d_in[4];
    const float* att1 = (const float*)d_in[5];
    const float* b1   = (const float*)d_in[6];
    const float* Wl2  = (const float*)d_in[7];
    const float* bl2  = (const float*)d_in[8];
    const float* Wr2  = (const float*)d_in[9];
    const float* br2  = (const float*)d_in[10];
    const float* att2 = (const float*)d_in[11];
    const float* b2   = (const float*)d_in[12];
    const float* Wc   = (const float*)d_in[13];
    const float* bc   = (const float*)d_in[14];
    const int*   ei   = (const int*)d_in[15];
    const int*   batch = (const int*)d_in[16];

    int N    = in_sizes[16];
    int E0   = in_sizes[15] / 2;
    int Etot = E0 + N;
    const int* srcA = ei;
    const int* dstA = ei + E0;

    __half2* xl2;
    float *xr, *pool, *cnt;
    int *deg, *off, *cur, *csrc;
    __nv_bfloat16 *xhi, *xlo, *hhi, *hlo;
    __nv_bfloat16 *wl1h, *wl1l, *wr1h, *wr1l, *wl2h, *wl2l, *wr2h, *wr2l;
    cudaGetSymbolAddress((void**)&xl2, d_xl2);
    cudaGetSymbolAddress((void**)&xr, d_xr);
    cudaGetSymbolAddress((void**)&deg, d_deg);
    cudaGetSymbolAddress((void**)&off, d_off);
    cudaGetSymbolAddress((void**)&cur, d_cur);
    cudaGetSymbolAddress((void**)&csrc, d_csrc);
    cudaGetSymbolAddress((void**)&pool, d_pool);
    cudaGetSymbolAddress((void**)&cnt, d_cnt);
    cudaGetSymbolAddress((void**)&xhi, d_xhi);
    cudaGetSymbolAddress((void**)&xlo, d_xlo);
    cudaGetSymbolAddress((void**)&hhi, d_hhi);
    cudaGetSymbolAddress((void**)&hlo, d_hlo);
    cudaGetSymbolAddress((void**)&wl1h, d_wl1hi);
    cudaGetSymbolAddress((void**)&wl1l, d_wl1lo);
    cudaGetSymbolAddress((void**)&wr1h, d_wr1hi);
    cudaGetSymbolAddress((void**)&wr1l, d_wr1lo);
    cudaGetSymbolAddress((void**)&wl2h, d_wl2hi);
    cudaGetSymbolAddress((void**)&wl2l, d_wl2lo);
    cudaGetSymbolAddress((void**)&wr2h, d_wr2hi);
    cudaGetSymbolAddress((void**)&wr2l, d_wr2lo);

    static bool attr_done = false;
    if (!attr_done) {
        cudaFuncSetAttribute(k_gemm_mma<128>, cudaFuncAttributeMaxDynamicSharedMemorySize,
                             2 * STAGE_BYTES);
        cudaFuncSetAttribute(k_gemm_mma<32>, cudaFuncAttributeMaxDynamicSharedMemorySize,
                             STAGE_BYTES);
        attr_done = true;
    }

    cudaStream_t s2 = g_side.s;
    int mt = (N + 127) / 128;
    int NX = N * 128;
    int split_total = NX + 163840;

    cudaEventRecord(g_side.ev_fork, 0);
    cudaStreamWaitEvent(s2, g_side.ev_fork, 0);

    // main stream: merged split + GEMM1
    k_split_all<<<(split_total + 255) / 256, 256>>>(
        x, NX, Wl1, Wr1, Wl2, Wr2,
        xhi, xlo, wl1h, wl1l, wr1h, wr1l, wl2h, wl2l, wr2h, wr2l);
    k_gemm_mma<128><<<dim3(16, mt), 256, 2 * STAGE_BYTES>>>(
        xhi, xlo, wl1h, wl1l, wr1h, wr1l, bl1, br1, xl2, xr, N);

    // side stream: CSR build + pool zero (overlaps)
    k_zero_csr<<<(N + 255) / 256, 256, 0, s2>>>(deg, cur, N);
    k_zero_pool<<<(TG * 32 + 255) / 256, 256, 0, s2>>>(pool, cnt);
    k_count<<<(Etot + 255) / 256, 256, 0, s2>>>(dstA, E0, Etot, deg);
    k_scan<<<1, 1024, 0, s2>>>(deg, off, N);
    k_scatter<<<(Etot + 255) / 256, 256, 0, s2>>>(srcA, dstA, E0, Etot, off, cur, csrc);
    cudaEventRecord(g_side.ev_join, s2);

    cudaStreamWaitEvent(0, g_side.ev_join, 0);

    // layer 1 edge pass -> bf16 split of h1
    k_fused<<<(N + 7) / 8, 256>>>(xl2, xr, att1, off, csrc, b1,
                                  hhi, hlo, nullptr, nullptr, nullptr, N);

    // layer 2
    k_gemm_mma<32><<<dim3(16, mt), 256, STAGE_BYTES>>>(
        hhi, hlo, wl2h, wl2l, wr2h, wr2l, bl2, br2, xl2, xr, N);
    // layer 2 edge pass -> fused global mean pool
    k_fused<<<(N + 7) / 8, 256>>>(xl2, xr, att2, off, csrc, b2,
                                  nullptr, nullptr, batch, pool, cnt, N);

    k_logits<<<1, 640>>>(pool, cnt, Wc, bc, (float*)d_out);
}